// round 11
// baseline (speedup 1.0000x reference)
#include <cuda_runtime.h>
#include <math_constants.h>

#define N_NODES 50000
#define N_EDGES 800000
#define D 64
#define DH 8
#define NSEG (N_NODES * DH)

typedef unsigned long long u64;

// Device scratch (no cudaMalloc allowed)
__device__ __align__(16) float g_q[N_NODES * D];
__device__ __align__(16) float g_k[N_NODES * D];
__device__ __align__(16) float g_s[NSEG];

// ---- Blackwell packed f32x2 helpers (FFMA2: only reachable via PTX) ----
__device__ __forceinline__ u64 pack2(float lo, float hi) {
    u64 r; asm("mov.b64 %0, {%1, %2};" : "=l"(r) : "f"(lo), "f"(hi)); return r;
}
__device__ __forceinline__ u64 fma2(u64 a, u64 b, u64 c) {
    u64 r; asm("fma.rn.f32x2 %0, %1, %2, %3;" : "=l"(r) : "l"(a), "l"(b), "l"(c)); return r;
}
__device__ __forceinline__ u64 add2(u64 a, u64 b) {
    u64 r; asm("add.rn.f32x2 %0, %1, %2;" : "=l"(r) : "l"(a), "l"(b)); return r;
}

// ---------------------------------------------------------------------------
// QK GEMM: x[N,64] @ {Wq,Wk}[64,64] + bias. 128 thr, 64 nodes/block,
// thread tile 4 cols x 8 nodes x 2 mats. 48KB smem -> 4 blocks/SM.
// Also zero-inits g_s.
// ---------------------------------------------------------------------------
__global__ __launch_bounds__(128, 4) void qk_gemm_kernel(
    const float* __restrict__ x,
    const float* __restrict__ Wq, const float* __restrict__ bq,
    const float* __restrict__ Wk, const float* __restrict__ bk)
{
    __shared__ __align__(16) float sW[2 * D * D];   // Wq | Wk
    __shared__ __align__(16) float sx[64 * D];

    const int tid = threadIdx.x;
    const int n0 = blockIdx.x * 64;

    // Fused init: zero g_s (100000 float4; 782*128 = 100096 thr)
    {
        int gtid = blockIdx.x * 128 + tid;
        if (gtid < NSEG / 4) {
            ((float4*)g_s)[gtid] = make_float4(0.f, 0.f, 0.f, 0.f);
        }
    }

    {
        const float4* wq4 = (const float4*)Wq;
        const float4* wk4 = (const float4*)Wk;
        float4* s4 = (float4*)sW;
#pragma unroll
        for (int i = tid; i < 1024; i += 128) {
            s4[i]        = wq4[i];
            s4[1024 + i] = wk4[i];
        }
    }
    {
        float4* sx4 = (float4*)sx;
        const float4* x4 = (const float4*)x;
#pragma unroll
        for (int i = tid; i < 1024; i += 128) {
            int node = i >> 4;
            int gn = n0 + node;
            sx4[i] = (gn < N_NODES) ? x4[(size_t)gn * 16 + (i & 15)]
                                    : make_float4(0.f, 0.f, 0.f, 0.f);
        }
    }
    __syncthreads();

    const int cx = (tid & 15) * 4;
    const int ny = tid >> 4;

    u64 acc[2][8][2];
#pragma unroll
    for (int m = 0; m < 2; m++)
#pragma unroll
        for (int j = 0; j < 8; j++) { acc[m][j][0] = 0ull; acc[m][j][1] = 0ull; }

#pragma unroll 4
    for (int i4 = 0; i4 < 16; i4++) {
        float xa[8][4];
#pragma unroll
        for (int j = 0; j < 8; j++) {
            *(float4*)xa[j] = *(const float4*)&sx[(ny + 8 * j) * D + i4 * 4];
        }
#pragma unroll
        for (int ii = 0; ii < 4; ii++) {
            const int i = i4 * 4 + ii;
            ulonglong2 wq = *(const ulonglong2*)&sW[i * D + cx];
            ulonglong2 wk = *(const ulonglong2*)&sW[D * D + i * D + cx];
#pragma unroll
            for (int j = 0; j < 8; j++) {
                float xs = xa[j][ii];
                u64 x2 = pack2(xs, xs);
                acc[0][j][0] = fma2(x2, wq.x, acc[0][j][0]);
                acc[0][j][1] = fma2(x2, wq.y, acc[0][j][1]);
                acc[1][j][0] = fma2(x2, wk.x, acc[1][j][0]);
                acc[1][j][1] = fma2(x2, wk.y, acc[1][j][1]);
            }
        }
    }

    ulonglong2 bq2 = *(const ulonglong2*)&bq[cx];
    ulonglong2 bk2 = *(const ulonglong2*)&bk[cx];

#pragma unroll
    for (int j = 0; j < 8; j++) {
        int node = n0 + ny + 8 * j;
        if (node < N_NODES) {
            *(u64*)&g_q[node * D + cx]     = add2(acc[0][j][0], bq2.x);
            *(u64*)&g_q[node * D + cx + 2] = add2(acc[0][j][1], bq2.y);
            *(u64*)&g_k[node * D + cx]     = add2(acc[1][j][0], bk2.x);
            *(u64*)&g_k[node * D + cx + 2] = add2(acc[1][j][1], bk2.y);
        }
    }
}

// ---------------------------------------------------------------------------
// V GEMM: x[N,64] @ Wv[64,64] + bias -> vout. Runs on a side stream,
// overlapped with edge_fused (fma-bound vs gather-bound: complementary).
// ---------------------------------------------------------------------------
__global__ __launch_bounds__(128, 6) void v_gemm_kernel(
    const float* __restrict__ x,
    const float* __restrict__ Wv, const float* __restrict__ bv,
    float* __restrict__ vout)
{
    __shared__ __align__(16) float sW[D * D];
    __shared__ __align__(16) float sx[64 * D];

    const int tid = threadIdx.x;
    const int n0 = blockIdx.x * 64;

    {
        const float4* wv4 = (const float4*)Wv;
        float4* s4 = (float4*)sW;
#pragma unroll
        for (int i = tid; i < 1024; i += 128) s4[i] = wv4[i];
    }
    {
        float4* sx4 = (float4*)sx;
        const float4* x4 = (const float4*)x;
#pragma unroll
        for (int i = tid; i < 1024; i += 128) {
            int node = i >> 4;
            int gn = n0 + node;
            sx4[i] = (gn < N_NODES) ? x4[(size_t)gn * 16 + (i & 15)]
                                    : make_float4(0.f, 0.f, 0.f, 0.f);
        }
    }
    __syncthreads();

    const int cx = (tid & 15) * 4;
    const int ny = tid >> 4;

    u64 acc[8][2];
#pragma unroll
    for (int j = 0; j < 8; j++) { acc[j][0] = 0ull; acc[j][1] = 0ull; }

#pragma unroll 4
    for (int i4 = 0; i4 < 16; i4++) {
        float xa[8][4];
#pragma unroll
        for (int j = 0; j < 8; j++) {
            *(float4*)xa[j] = *(const float4*)&sx[(ny + 8 * j) * D + i4 * 4];
        }
#pragma unroll
        for (int ii = 0; ii < 4; ii++) {
            const int i = i4 * 4 + ii;
            ulonglong2 wv = *(const ulonglong2*)&sW[i * D + cx];
#pragma unroll
            for (int j = 0; j < 8; j++) {
                float xs = xa[j][ii];
                u64 x2 = pack2(xs, xs);
                acc[j][0] = fma2(x2, wv.x, acc[j][0]);
                acc[j][1] = fma2(x2, wv.y, acc[j][1]);
            }
        }
    }

    ulonglong2 bv2 = *(const ulonglong2*)&bv[cx];

#pragma unroll
    for (int j = 0; j < 8; j++) {
        int node = n0 + ny + 8 * j;
        if (node < N_NODES) {
            *(u64*)&vout[node * D + cx]     = add2(acc[j][0], bv2.x);
            *(u64*)&vout[node * D + cx + 2] = add2(acc[j][1], bv2.y);
        }
    }
}

// ---------------------------------------------------------------------------
// Warp-cooperative fused edge pass: logits + exp + vec4-atomic segment sum.
// 8 lanes per edge, 4 edges per warp; all gathers coalesced.
// ---------------------------------------------------------------------------
__global__ __launch_bounds__(256) void edge_fused_kernel(
    const int* __restrict__ edge, float* __restrict__ prods)
{
    const int lane = threadIdx.x & 31;
    const int warp = (blockIdx.x * 256 + threadIdx.x) >> 5;
    const int e0   = warp * 4;
    const int sub  = lane >> 3;
    const int d    = lane & 7;
    const int e    = e0 + sub;

    const int src = edge[e];
    const int dst = edge[N_EDGES + e];

    const float4* q4 = (const float4*)(g_q + src * D);
    const float4* k4 = (const float4*)(g_k + dst * D);

    float4 qa = q4[d];
    float4 qb = q4[d + 8];
    float4 ka = k4[d];
    float4 kb = k4[d + 8];

    float w0 = qa.x * ka.x + qb.x * kb.x;
    float w1 = qa.y * ka.y + qb.y * kb.y;
    float w2 = qa.z * ka.z + qb.z * kb.z;
    float w3 = qa.w * ka.w + qb.w * kb.w;

    const unsigned FULL = 0xffffffffu;

    {
        float t0 = (lane & 4) ? w0 : w2;
        float t1 = (lane & 4) ? w1 : w3;
        float u0 = __shfl_xor_sync(FULL, t0, 4);
        float u1 = __shfl_xor_sync(FULL, t1, 4);
        w0 = ((lane & 4) ? w2 : w0) + u0;
        w1 = ((lane & 4) ? w3 : w1) + u1;
    }
    float p;
    {
        float t2 = (lane & 2) ? w0 : w1;
        float u2 = __shfl_xor_sync(FULL, t2, 2);
        p = ((lane & 2) ? w1 : w0) + u2;
    }
    {
        int srcl = (sub << 3) | ((d >> 2) & 1) | ((d & 1) << 1) | ((d & 2) << 1);
        p = __shfl_sync(FULL, p, srcl);
    }

    p *= 0.35355339059327373f;  // 1/sqrt(8)

    size_t off = (size_t)e0 * 8 + lane;
    prods[off] = p;
    float ev = __expf(p);

    float p1 = __shfl_down_sync(FULL, ev, 1);
    float p2 = __shfl_down_sync(FULL, ev, 2);
    float p3 = __shfl_down_sync(FULL, ev, 3);
    if ((lane & 3) == 0) {
        float* srow = g_s + dst * 8 + (lane & 4);
        asm volatile("red.global.add.v4.f32 [%0], {%1, %2, %3, %4};"
                     :: "l"(srow), "f"(ev), "f"(p1), "f"(p2), "f"(p3) : "memory");
    }
}

// ---------------------------------------------------------------------------
// Pass C: att[e][d] = exp(prods[e][d]) / (s[dst][d] + 1e-16).
// 2 edges per thread (doubled MLP on the scattered g_s gather and the
// prods/att streams; same inst/byte ratio as the 15us 1-edge form).
// ---------------------------------------------------------------------------
__global__ __launch_bounds__(256) void edge_scale_kernel(
    const int* __restrict__ edge, const float* __restrict__ prods,
    float* __restrict__ att)
{
    int t = blockIdx.x * blockDim.x + threadIdx.x;
    int e0 = t * 2;
    if (e0 >= N_EDGES) return;

    int dst0 = edge[N_EDGES + e0];
    int dst1 = edge[N_EDGES + e0 + 1];

    const float4* sr0 = (const float4*)(g_s + dst0 * 8);
    const float4* sr1 = (const float4*)(g_s + dst1 * 8);
    float4 sa0 = sr0[0], sa1 = sr0[1];
    float4 sb0 = sr1[0], sb1 = sr1[1];

    const float4* pr = (const float4*)(prods + (size_t)e0 * 8);
    float4 pa0 = pr[0], pa1 = pr[1], pb0 = pr[2], pb1 = pr[3];

    float4 va0, va1, vb0, vb1;
    va0.x = __fdividef(__expf(pa0.x), sa0.x + 1e-16f);
    va0.y = __fdividef(__expf(pa0.y), sa0.y + 1e-16f);
    va0.z = __fdividef(__expf(pa0.z), sa0.z + 1e-16f);
    va0.w = __fdividef(__expf(pa0.w), sa0.w + 1e-16f);
    va1.x = __fdividef(__expf(pa1.x), sa1.x + 1e-16f);
    va1.y = __fdividef(__expf(pa1.y), sa1.y + 1e-16f);
    va1.z = __fdividef(__expf(pa1.z), sa1.z + 1e-16f);
    va1.w = __fdividef(__expf(pa1.w), sa1.w + 1e-16f);
    vb0.x = __fdividef(__expf(pb0.x), sb0.x + 1e-16f);
    vb0.y = __fdividef(__expf(pb0.y), sb0.y + 1e-16f);
    vb0.z = __fdividef(__expf(pb0.z), sb0.z + 1e-16f);
    vb0.w = __fdividef(__expf(pb0.w), sb0.w + 1e-16f);
    vb1.x = __fdividef(__expf(pb1.x), sb1.x + 1e-16f);
    vb1.y = __fdividef(__expf(pb1.y), sb1.y + 1e-16f);
    vb1.z = __fdividef(__expf(pb1.z), sb1.z + 1e-16f);
    vb1.w = __fdividef(__expf(pb1.w), sb1.w + 1e-16f);

    float4* ar = (float4*)(att + (size_t)e0 * 8);
    ar[0] = va0;
    ar[1] = va1;
    ar[2] = vb0;
    ar[3] = vb1;
}

// ---------------------------------------------------------------------------
// kernel_launch
// Inputs (metadata order): x, Wq, bq, Wk, bk, Wv, bv, edge
// Output: attention [E,8] | v [N,8,8] | prods [E,8]  (float32)
//
// Stream plan: qk_gemm on the capture stream (0); then fork into TWO created
// non-blocking streams (sA: edge path, s2: v_gemm) so neither branch touches
// the legacy stream (whose implicit-sync semantics serialized R10's graph);
// join both back to 0 at the end.
// ---------------------------------------------------------------------------
extern "C" void kernel_launch(void* const* d_in, const int* in_sizes, int n_in,
                              void* d_out, int out_size) {
    const float* x  = (const float*)d_in[0];
    const float* Wq = (const float*)d_in[1];
    const float* bq = (const float*)d_in[2];
    const float* Wk = (const float*)d_in[3];
    const float* bk = (const float*)d_in[4];
    const float* Wv = (const float*)d_in[5];
    const float* bv = (const float*)d_in[6];
    const int*   edge = (const int*)d_in[7];

    float* out   = (float*)d_out;
    float* att   = out;                          // E*8
    float* vout  = out + (size_t)N_EDGES * 8;    // N*64
    float* prods = vout + (size_t)N_NODES * 64;  // E*8

    // Lazy one-time creation of side streams + events (host objects only).
    static cudaStream_t sA = nullptr, s2 = nullptr;
    static cudaEvent_t evFork = nullptr, evJoinA = nullptr, evJoinV = nullptr;
    if (sA == nullptr) {
        cudaStreamCreateWithFlags(&sA, cudaStreamNonBlocking);
        cudaStreamCreateWithFlags(&s2, cudaStreamNonBlocking);
        cudaEventCreateWithFlags(&evFork, cudaEventDisableTiming);
        cudaEventCreateWithFlags(&evJoinA, cudaEventDisableTiming);
        cudaEventCreateWithFlags(&evJoinV, cudaEventDisableTiming);
    }

    qk_gemm_kernel<<<(N_NODES + 63) / 64, 128>>>(x, Wq, bq, Wk, bk);

    // Fork both branches off the capture stream.
    cudaEventRecord(evFork, 0);
    cudaStreamWaitEvent(sA, evFork, 0);
    cudaStreamWaitEvent(s2, evFork, 0);

    // Branch V (independent of edge path).
    v_gemm_kernel<<<(N_NODES + 63) / 64, 128, 0, s2>>>(x, Wv, bv, vout);
    cudaEventRecord(evJoinV, s2);

    // Branch edge path.
    edge_fused_kernel<<<N_EDGES / 32, 256, 0, sA>>>(edge, prods);
    edge_scale_kernel<<<(N_EDGES / 2 + 255) / 256, 256, 0, sA>>>(edge, prods, att);
    cudaEventRecord(evJoinA, sA);

    // Join both branches to the capture stream.
    cudaStreamWaitEvent(0, evJoinA, 0);
    cudaStreamWaitEvent(0, evJoinV, 0);
}

// round 12
// speedup vs baseline: 1.1330x; 1.1330x over previous
#include <cuda_runtime.h>
#include <math_constants.h>

#define N_NODES 50000
#define N_EDGES 800000
#define D 64
#define DH 8
#define NSEG (N_NODES * DH)
#define NPB 96   // nodes per gemm block

typedef unsigned long long u64;

// Device scratch (no cudaMalloc allowed)
__device__ __align__(16) float g_q[N_NODES * D];
__device__ __align__(16) float g_k[N_NODES * D];
__device__ __align__(16) float g_s[NSEG];

// ---- Blackwell packed f32x2 helpers (FFMA2: only reachable via PTX) ----
__device__ __forceinline__ u64 pack2(float lo, float hi) {
    u64 r; asm("mov.b64 %0, {%1, %2};" : "=l"(r) : "f"(lo), "f"(hi)); return r;
}
__device__ __forceinline__ u64 fma2(u64 a, u64 b, u64 c) {
    u64 r; asm("fma.rn.f32x2 %0, %1, %2, %3;" : "=l"(r) : "l"(a), "l"(b), "l"(c)); return r;
}
__device__ __forceinline__ u64 add2(u64 a, u64 b) {
    u64 r; asm("add.rn.f32x2 %0, %1, %2;" : "=l"(r) : "l"(a), "l"(b)); return r;
}

// ---------------------------------------------------------------------------
// Fused QKV GEMM: x[N,64] @ {Wq,Wk,Wv}[64,64] + bias, packed f32x2 FMA.
// 128 thr/block, 96 nodes/block. Thread tile: 4 cols x 12 nodes x 3 mats.
// Per k-step per thread: 3 W-LDS.128 + 3 x-LDS.128 feed 72 fma2
// (0.083 LDS/MAC, 20% less than the R7 8-node tile).
// smem 72KB -> 2 blocks/SM; launch_bounds(128,2) -> up to 255 regs (no spill).
// Also zero-inits g_s (fused; 2 float4 per thread).
// ---------------------------------------------------------------------------
__global__ __launch_bounds__(128, 2) void qkv_gemm_kernel(
    const float* __restrict__ x,
    const float* __restrict__ Wq, const float* __restrict__ bq,
    const float* __restrict__ Wk, const float* __restrict__ bk,
    const float* __restrict__ Wv, const float* __restrict__ bv,
    float* __restrict__ vout)
{
    __shared__ __align__(16) float sW[3 * D * D];   // Wq | Wk | Wv (row-major [i][col])
    __shared__ __align__(16) float sx[NPB * D];     // 96 nodes x 64 feats

    const int tid = threadIdx.x;
    const int n0 = blockIdx.x * NPB;

    // Fused init: zero g_s (100000 float4; 521 blocks * 128 thr * 2 = 133376)
    {
        int gtid = blockIdx.x * 128 + tid;
        if (gtid < NSEG / 4) ((float4*)g_s)[gtid] = make_float4(0.f, 0.f, 0.f, 0.f);
        gtid += 521 * 128;
        if (gtid < NSEG / 4) ((float4*)g_s)[gtid] = make_float4(0.f, 0.f, 0.f, 0.f);
    }

    // Load weights via float4 (1024 float4 per matrix)
    {
        const float4* wq4 = (const float4*)Wq;
        const float4* wk4 = (const float4*)Wk;
        const float4* wv4 = (const float4*)Wv;
        float4* s4 = (float4*)sW;
#pragma unroll
        for (int i = tid; i < 1024; i += 128) {
            s4[i]        = wq4[i];
            s4[1024 + i] = wk4[i];
            s4[2048 + i] = wv4[i];
        }
    }
    // Load x tile (96 nodes x 64 = 1536 float4)
    {
        float4* sx4 = (float4*)sx;
        const float4* x4 = (const float4*)x;
#pragma unroll
        for (int i = tid; i < NPB * 16; i += 128) {
            int node = i >> 4;
            int gn = n0 + node;
            sx4[i] = (gn < N_NODES) ? x4[(size_t)gn * 16 + (i & 15)]
                                    : make_float4(0.f, 0.f, 0.f, 0.f);
        }
    }
    __syncthreads();

    const int cx = (tid & 15) * 4;   // 4 consecutive output cols (16B aligned)
    const int ny = tid >> 4;         // node row 0..7; nodes ny + 8*j, j=0..11

    u64 acc[3][12][2];
#pragma unroll
    for (int m = 0; m < 3; m++)
#pragma unroll
        for (int j = 0; j < 12; j++) { acc[m][j][0] = 0ull; acc[m][j][1] = 0ull; }

#pragma unroll 2
    for (int i4 = 0; i4 < 16; i4++) {
        // x values for 12 nodes x 4 k-steps (broadcast LDS.128)
        float xa[12][4];
#pragma unroll
        for (int j = 0; j < 12; j++) {
            *(float4*)xa[j] = *(const float4*)&sx[(ny + 8 * j) * D + i4 * 4];
        }
#pragma unroll
        for (int ii = 0; ii < 4; ii++) {
            const int i = i4 * 4 + ii;
            ulonglong2 wq = *(const ulonglong2*)&sW[i * D + cx];
            ulonglong2 wk = *(const ulonglong2*)&sW[D * D + i * D + cx];
            ulonglong2 wv = *(const ulonglong2*)&sW[2 * D * D + i * D + cx];
#pragma unroll
            for (int j = 0; j < 12; j++) {
                float xs = xa[j][ii];
                u64 x2 = pack2(xs, xs);
                acc[0][j][0] = fma2(x2, wq.x, acc[0][j][0]);
                acc[0][j][1] = fma2(x2, wq.y, acc[0][j][1]);
                acc[1][j][0] = fma2(x2, wk.x, acc[1][j][0]);
                acc[1][j][1] = fma2(x2, wk.y, acc[1][j][1]);
                acc[2][j][0] = fma2(x2, wv.x, acc[2][j][0]);
                acc[2][j][1] = fma2(x2, wv.y, acc[2][j][1]);
            }
        }
    }

    // Bias straight from global (L1/const cached, 16B aligned at cx)
    ulonglong2 bq2 = *(const ulonglong2*)&bq[cx];
    ulonglong2 bk2 = *(const ulonglong2*)&bk[cx];
    ulonglong2 bv2 = *(const ulonglong2*)&bv[cx];

#pragma unroll
    for (int j = 0; j < 12; j++) {
        int node = n0 + ny + 8 * j;
        if (node < N_NODES) {
            *(u64*)&g_q[node * D + cx]      = add2(acc[0][j][0], bq2.x);
            *(u64*)&g_q[node * D + cx + 2]  = add2(acc[0][j][1], bq2.y);
            *(u64*)&g_k[node * D + cx]      = add2(acc[1][j][0], bk2.x);
            *(u64*)&g_k[node * D + cx + 2]  = add2(acc[1][j][1], bk2.y);
            *(u64*)&vout[node * D + cx]     = add2(acc[2][j][0], bv2.x);
            *(u64*)&vout[node * D + cx + 2] = add2(acc[2][j][1], bv2.y);
        }
    }
}

// ---------------------------------------------------------------------------
// Warp-cooperative fused edge pass: logits + exp + vec4-atomic segment sum.
// 8 lanes per edge, 4 edges per warp; all gathers coalesced. No att write
// (edge_scale recomputes exp from prods).
// ---------------------------------------------------------------------------
__global__ __launch_bounds__(256) void edge_fused_kernel(
    const int* __restrict__ edge, float* __restrict__ prods)
{
    const int lane = threadIdx.x & 31;
    const int warp = (blockIdx.x * 256 + threadIdx.x) >> 5;
    const int e0   = warp * 4;
    const int sub  = lane >> 3;
    const int d    = lane & 7;
    const int e    = e0 + sub;

    const int src = edge[e];
    const int dst = edge[N_EDGES + e];

    const float4* q4 = (const float4*)(g_q + src * D);
    const float4* k4 = (const float4*)(g_k + dst * D);

    float4 qa = q4[d];
    float4 qb = q4[d + 8];
    float4 ka = k4[d];
    float4 kb = k4[d + 8];

    float w0 = qa.x * ka.x + qb.x * kb.x;
    float w1 = qa.y * ka.y + qb.y * kb.y;
    float w2 = qa.z * ka.z + qb.z * kb.z;
    float w3 = qa.w * ka.w + qb.w * kb.w;

    const unsigned FULL = 0xffffffffu;

    {
        float t0 = (lane & 4) ? w0 : w2;
        float t1 = (lane & 4) ? w1 : w3;
        float u0 = __shfl_xor_sync(FULL, t0, 4);
        float u1 = __shfl_xor_sync(FULL, t1, 4);
        w0 = ((lane & 4) ? w2 : w0) + u0;
        w1 = ((lane & 4) ? w3 : w1) + u1;
    }
    float p;
    {
        float t2 = (lane & 2) ? w0 : w1;
        float u2 = __shfl_xor_sync(FULL, t2, 2);
        p = ((lane & 2) ? w1 : w0) + u2;
    }
    {
        int srcl = (sub << 3) | ((d >> 2) & 1) | ((d & 1) << 1) | ((d & 2) << 1);
        p = __shfl_sync(FULL, p, srcl);
    }

    p *= 0.35355339059327373f;  // 1/sqrt(8)

    size_t off = (size_t)e0 * 8 + lane;
    prods[off] = p;
    float ev = __expf(p);

    float p1 = __shfl_down_sync(FULL, ev, 1);
    float p2 = __shfl_down_sync(FULL, ev, 2);
    float p3 = __shfl_down_sync(FULL, ev, 3);
    if ((lane & 3) == 0) {
        float* srow = g_s + dst * 8 + (lane & 4);
        asm volatile("red.global.add.v4.f32 [%0], {%1, %2, %3, %4};"
                     :: "l"(srow), "f"(ev), "f"(p1), "f"(p2), "f"(p3) : "memory");
    }
}

// ---------------------------------------------------------------------------
// Pass C (R9 1-edge form, measured 15us):
// att[e][d] = exp(prods[e][d]) / (s[dst][d] + 1e-16), float4 vectorized.
// ---------------------------------------------------------------------------
__global__ __launch_bounds__(256) void edge_scale_kernel(
    const int* __restrict__ edge, const float* __restrict__ prods,
    float* __restrict__ att)
{
    int e = blockIdx.x * blockDim.x + threadIdx.x;
    if (e >= N_EDGES) return;
    int dst = edge[N_EDGES + e];

    const float4* sr = (const float4*)(g_s + dst * 8);
    float4 s0 = sr[0];
    float4 s1 = sr[1];

    const float4* pr = (const float4*)(prods + (size_t)e * 8);
    float4 p0 = pr[0];
    float4 p1 = pr[1];

    float4 v0, v1;
    v0.x = __fdividef(__expf(p0.x), s0.x + 1e-16f);
    v0.y = __fdividef(__expf(p0.y), s0.y + 1e-16f);
    v0.z = __fdividef(__expf(p0.z), s0.z + 1e-16f);
    v0.w = __fdividef(__expf(p0.w), s0.w + 1e-16f);
    v1.x = __fdividef(__expf(p1.x), s1.x + 1e-16f);
    v1.y = __fdividef(__expf(p1.y), s1.y + 1e-16f);
    v1.z = __fdividef(__expf(p1.z), s1.z + 1e-16f);
    v1.w = __fdividef(__expf(p1.w), s1.w + 1e-16f);

    float4* ar = (float4*)(att + (size_t)e * 8);
    ar[0] = v0;
    ar[1] = v1;
}

// ---------------------------------------------------------------------------
// kernel_launch — single stream (overlap experiments reverted: block-level
// co-scheduling conserved SM-seconds and only added event overhead).
// Inputs (metadata order): x, Wq, bq, Wk, bk, Wv, bv, edge
// Output: attention [E,8] | v [N,8,8] | prods [E,8]  (float32)
// ---------------------------------------------------------------------------
extern "C" void kernel_launch(void* const* d_in, const int* in_sizes, int n_in,
                              void* d_out, int out_size) {
    const float* x  = (const float*)d_in[0];
    const float* Wq = (const float*)d_in[1];
    const float* bq = (const float*)d_in[2];
    const float* Wk = (const float*)d_in[3];
    const float* bk = (const float*)d_in[4];
    const float* Wv = (const float*)d_in[5];
    const float* bv = (const float*)d_in[6];
    const int*   edge = (const int*)d_in[7];

    float* out   = (float*)d_out;
    float* att   = out;                          // E*8
    float* vout  = out + (size_t)N_EDGES * 8;    // N*64
    float* prods = vout + (size_t)N_NODES * 64;  // E*8

    qkv_gemm_kernel<<<(N_NODES + NPB - 1) / NPB, 128>>>(x, Wq, bq, Wk, bk, Wv, bv, vout);
    edge_fused_kernel<<<N_EDGES / 32, 256>>>(edge, prods);
    edge_scale_kernel<<<(N_EDGES + 255) / 256, 256>>>(edge, prods, att);
}